// round 13
// baseline (speedup 1.0000x reference)
#include <cuda_runtime.h>

#define DECAYF 0.951229424500714f   // exp(-1/20)

// Persistent state (no allocs allowed)
__device__ float g_vm0[2097152];      // [16 b][32 o][64][64]
__device__ float g_s0f[2097152];
__device__ float g_vm1[4194304];      // [16 b][64 o][64][64]
__device__ float g_flatT[1048576];    // pooled spikes [i=65536][b=16]
__device__ float g_part[524288];      // dense0 partials [is=64][b=16][j=512]
__device__ float g_vm2[8192];         // [b][j]
__device__ float g_vm3[176], g_acc[176];
__device__ float g_nop[32];

// ---- packed f32x2 helpers ----
__device__ __forceinline__ unsigned long long pack2(float a, float b) {
    unsigned long long r;
    asm("mov.b64 %0, {%1, %2};" : "=l"(r)
        : "r"(__float_as_uint(a)), "r"(__float_as_uint(b)));
    return r;
}
__device__ __forceinline__ void unpack2(unsigned long long v, float& a, float& b) {
    unsigned lo, hi;
    asm("mov.b64 {%0, %1}, %2;" : "=r"(lo), "=r"(hi) : "l"(v));
    a = __uint_as_float(lo); b = __uint_as_float(hi);
}
#define FMA2(acc, w, s) asm("fma.rn.f32x2 %0, %1, %2, %0;" : "+l"(acc) : "l"(w), "l"(s))
#define ADD2(acc, v)    asm("add.rn.f32x2 %0, %0, %1;"      : "+l"(acc) : "l"(v))

// dummy kernel: 2 nops -> ncu-captured launch (#3) = k_conv1(t=0)
__global__ void k_nop() { g_nop[threadIdx.x] = 0.f; }

// ---------------------------------------------------------------------------
// conv0 (2->32, 3x3 pad1) + LIF0.  grid = 16 b * 32 o = 512 blocks, 256 thr.
// ---------------------------------------------------------------------------
__global__ void __launch_bounds__(256) k_conv0(const float* __restrict__ in,
                                               const float* __restrict__ W0, int t)
{
    int bid = blockIdx.x;
    int o = bid & 31, b = bid >> 5;
    float w[18];
#pragma unroll
    for (int i = 0; i < 18; i++) w[i] = W0[o * 18 + i];
    const float* x0 = in + (((long)(b * 16 + t)) << 13);

#pragma unroll 4
    for (int p = threadIdx.x; p < 4096; p += 256) {
        int y = p >> 6, x = p & 63;
        float acc = 0.f;
#pragma unroll
        for (int c = 0; c < 2; c++)
#pragma unroll
            for (int ky = 0; ky < 3; ky++) {
                int yy = y + ky - 1;
                if ((unsigned)yy < 64u)
#pragma unroll
                    for (int kx = 0; kx < 3; kx++) {
                        int xx = x + kx - 1;
                        if ((unsigned)xx < 64u) {
                            float v = x0[(c << 12) + (yy << 6) + xx];
                            v = fminf(fmaxf(v, 0.f), 1.f);
                            acc = fmaf(w[c * 9 + ky * 3 + kx], v, acc);
                        }
                    }
            }
        long idx = (((long)bid) << 12) + p;
        float vm;
        if (t) {
            float vp = g_vm0[idx];
            vm = vp * (vp > 0.5f ? 0.f : DECAYF) + acc;
        } else vm = acc;
        g_vm0[idx] = vm;
        g_s0f[idx] = vm > 0.5f ? 1.f : 0.f;
    }
}

// ---------------------------------------------------------------------------
// conv1 (32->64, 3x3) + LIF1 + fused 2x2 maxpool (binary OR) -> g_flatT.
// grid = 16 b * 8 tiles(16 rows x 32 cols) * 2 och-halves = 256 blocks,
// 256 threads. Thread: 4 och-pairs x 8 px = 32 f32x2 accumulators.
// Each weight LDS.128 pair now feeds 32 FFMA2 (2x reuse vs R12).
// smem: paired weights [ck=288][16] (36864B) + f32 halo chunk of 8 channels
//   [8][18][35] (20160B) = 57024B -> 3 blocks/SM.
// Spike rows loaded per-ky (s2[10] live) to stay under 128 regs.
// ---------------------------------------------------------------------------
__global__ void __launch_bounds__(256, 2) k_conv1(const float* __restrict__ W1, int t)
{
    extern __shared__ unsigned char sh1[];
    unsigned long long* wsm = (unsigned long long*)sh1;   // [ck=288][pair=16]
    float* ssm = (float*)(sh1 + 36864);                   // [cl=8][18][35]

    int bid  = blockIdx.x;
    int oh   = bid & 1;
    int tile = (bid >> 1) & 7;       // 4 ty x 2 tx
    int b    = bid >> 4;
    int ty0  = (tile >> 1) << 4;     // 0,16,32,48
    int tx0  = (tile & 1) << 5;      // 0,32
    int tid  = threadIdx.x;
    int pg   = tid >> 6;             // 0..3 : pair group (4 pairs = 8 och)
    int pxg  = tid & 63;
    int row  = pxg & 15;
    int cg   = pxg >> 4;             // 0..3
    int px0  = cg << 3;              // 0,8,16,24

    // weights: pair (o, o+1), o = oh*32 + 2*pr  (loaded once)
    for (int idx = tid; idx < 4608; idx += 256) {
        int ck = idx >> 4, pr = idx & 15;
        const float* wb = W1 + (oh * 32 + 2 * pr) * 288 + ck;
        wsm[ck * 16 + pr] = pack2(wb[0], wb[288]);
    }

    unsigned long long acc[32];      // [g=4][px=8]
#pragma unroll
    for (int i = 0; i < 32; i++) acc[i] = 0ull;

    for (int cc = 0; cc < 32; cc += 8) {
        if (cc) __syncthreads();     // all warps done with previous chunk
        // f32 spike halo for channels cc..cc+7, rows 18 x cols 34, stride 35
        for (int idx = tid; idx < 4896; idx += 256) {
            int cl = idx / 612, r = idx - cl * 612;
            int yy = r / 34, xx = r - yy * 34;
            int y = ty0 - 1 + yy, x = tx0 - 1 + xx;
            float v = 0.f;
            if ((unsigned)y < 64u && (unsigned)x < 64u)
                v = g_s0f[(((b << 5) + cc + cl) << 12) + (y << 6) + x];
            ssm[cl * 630 + yy * 35 + xx] = v;
        }
        __syncthreads();

        for (int cl = 0; cl < 8; ++cl) {
            int c = cc + cl;
            const float* base = ssm + cl * 630 + row * 35 + px0;
#pragma unroll
            for (int ky = 0; ky < 3; ++ky) {
                unsigned long long s2[10];
#pragma unroll
                for (int u = 0; u < 10; ++u) {
                    float s = base[ky * 35 + u];
                    s2[u] = pack2(s, s);
                }
#pragma unroll
                for (int kx = 0; kx < 3; ++kx) {
                    const ulonglong2* wp =
                        (const ulonglong2*)(wsm + (c * 9 + ky * 3 + kx) * 16 + (pg << 2));
                    ulonglong2 wa = wp[0], wbv = wp[1];
                    unsigned long long wv[4] = {wa.x, wa.y, wbv.x, wbv.y};
#pragma unroll
                    for (int g = 0; g < 4; ++g)
#pragma unroll
                        for (int px = 0; px < 8; ++px)
                            FMA2(acc[g * 8 + px], wv[g], s2[kx + px]);
                }
            }
        }
    }

    // LIF1 + pooled bits.  bit index = ol*4 + xp (ol = channel 0..7, xp 0..3).
    int y = ty0 + row, x = tx0 + px0;
    unsigned pool = 0u;
#pragma unroll
    for (int g = 0; g < 4; ++g) {
        int o0 = oh * 32 + (pg << 3) + 2 * g;
        long ibase = (((long)((b << 6) + o0)) << 12) + (y << 6) + x;
#pragma unroll
        for (int px = 0; px < 8; ++px) {
            float I0, I1; unpack2(acc[g * 8 + px], I0, I1);
            long i0 = ibase + px, i1 = i0 + 4096;
            float va, vb;
            if (t) {
                float vp0 = g_vm1[i0], vp1 = g_vm1[i1];
                va = vp0 * (vp0 > 0.5f ? 0.f : DECAYF) + I0;
                vb = vp1 * (vp1 > 0.5f ? 0.f : DECAYF) + I1;
            } else { va = I0; vb = I1; }
            g_vm1[i0] = va; g_vm1[i1] = vb;
            unsigned sa = va > 0.5f ? 1u : 0u;
            unsigned sb = vb > 0.5f ? 1u : 0u;
            int xp = px >> 1;
            pool |= (sa << ((2 * g) * 4 + xp));        // ol = 2g
            pool |= (sb << ((2 * g + 1) * 4 + xp));    // ol = 2g+1
        }
    }
    pool |= __shfl_xor_sync(0xffffffffu, pool, 1);     // row partner (y ^ 1)
    if ((row & 1) == 0) {
        int py = y >> 1, pxb = x >> 1;                 // pooled col base
#pragma unroll
        for (int ol = 0; ol < 8; ++ol) {
            int o = oh * 32 + (pg << 3) + ol;
            int base2 = (o << 10) + (py << 5) + pxb;
#pragma unroll
            for (int xp = 0; xp < 4; ++xp)
                g_flatT[((base2 + xp) << 4) + b] =
                    (float)((pool >> (ol * 4 + xp)) & 1u);
        }
    }
}

// ---------------------------------------------------------------------------
// dense0 partials (R7 version, measured 52.7us): thread = 4 j x 8 batch-pairs,
// k-interleaved spike smem (conflict-free LDS.64), D0 via LDG.128.
// ---------------------------------------------------------------------------
__global__ void __launch_bounds__(256, 2) k_dense0(const float* __restrict__ D0)
{
    extern __shared__ float sh[];                        // 64 KB
    unsigned long long* sb2 = (unsigned long long*)sh;
    int jt = blockIdx.x & 7;
    int is = blockIdx.x >> 3;
    int tid = threadIdx.x;
    int jq = tid >> 4, ig = tid & 15;
    int j0 = (jt << 6) + (jq << 2);

    {   // stage flat chunk: [1024 i][16 b] -> k-interleaved pair-major
        const uint2* src = (const uint2*)(g_flatT + ((long)is << 14));
        uint2* dst = (uint2*)sb2;
        for (int n = tid; n < 8192; n += 256) {
            int i = n >> 3, p = n & 7;
            dst[(p << 10) + ((i & 3) << 8) + (i >> 2)] = src[n];
        }
    }
    __syncthreads();

    unsigned long long acc[32];
#pragma unroll
    for (int q = 0; q < 32; q++) acc[q] = 0ull;

    const float4* dbase4 = (const float4*)(D0 + ((long)j0 << 16) + (is << 10));
#pragma unroll 2
    for (int n = 0; n < 16; ++n) {
        int i4 = ig + (n << 4);
        float4 a0 = dbase4[i4];
        float4 a1 = dbase4[16384 + i4];
        float4 a2 = dbase4[32768 + i4];
        float4 a3 = dbase4[49152 + i4];
        float r0[4] = {a0.x, a0.y, a0.z, a0.w};
        float r1[4] = {a1.x, a1.y, a1.z, a1.w};
        float r2[4] = {a2.x, a2.y, a2.z, a2.w};
        float r3[4] = {a3.x, a3.y, a3.z, a3.w};
#pragma unroll
        for (int k = 0; k < 4; ++k) {
            unsigned long long dd0 = pack2(r0[k], r0[k]);
            unsigned long long dd1 = pack2(r1[k], r1[k]);
            unsigned long long dd2 = pack2(r2[k], r2[k]);
            unsigned long long dd3 = pack2(r3[k], r3[k]);
#pragma unroll
            for (int p = 0; p < 8; ++p) {
                unsigned long long s = sb2[(p << 10) + (k << 8) + i4];
                FMA2(acc[p],      dd0, s);
                FMA2(acc[8 + p],  dd1, s);
                FMA2(acc[16 + p], dd2, s);
                FMA2(acc[24 + p], dd3, s);
            }
        }
    }
#pragma unroll
    for (int off = 8; off; off >>= 1)
#pragma unroll
        for (int q = 0; q < 32; q++) {
            unsigned long long v = __shfl_xor_sync(0xffffffffu, acc[q], off);
            ADD2(acc[q], v);
        }
    if (ig == 0) {
        // g_part layout: [is][b][j]
#pragma unroll
        for (int q = 0; q < 4; q++) {
            int j = j0 + q;
#pragma unroll
            for (int p = 0; p < 8; p++) {
                float a0, a1; unpack2(acc[q * 8 + p], a0, a1);
                g_part[(is << 13) + ((2 * p)     << 9) + j] = a0;
                g_part[(is << 13) + ((2 * p + 1) << 9) + j] = a1;
            }
        }
    }
}

// ---------------------------------------------------------------------------
// fused tail: per-batch block. lif2 reduce (coalesced over j) + dense1 + LIF3.
// grid = 16 (batch), 512 threads.
// ---------------------------------------------------------------------------
__global__ void __launch_bounds__(512) k_tail2(const float* __restrict__ D1,
                                               float* __restrict__ out, int t)
{
    __shared__ float s2[512];
    int b = blockIdx.x;
    int tid = threadIdx.x;     // = j
    float I = 0.f;
#pragma unroll 8
    for (int is = 0; is < 64; is++)
        I += g_part[(is << 13) + (b << 9) + tid];
    int idx = (b << 9) + tid;
    float vm;
    if (t) {
        float vp = g_vm2[idx];
        vm = vp * (vp > 0.5f ? 0.f : DECAYF) + I;
    } else vm = I;
    g_vm2[idx] = vm;
    s2[tid] = vm > 0.5f ? 1.f : 0.f;
    __syncthreads();

    int w = tid >> 5, lane = tid & 31;
    if (w < 11) {
        float acc = 0.f;
#pragma unroll
        for (int u = 0; u < 16; u++)
            acc = fmaf(s2[lane + (u << 5)], D1[(w << 9) + lane + (u << 5)], acc);
#pragma unroll
        for (int off = 16; off; off >>= 1)
            acc += __shfl_xor_sync(0xffffffffu, acc, off);
        if (lane == 0) {
            int oidx = b * 11 + w;
            float vm3;
            if (t) {
                float vp = g_vm3[oidx];
                vm3 = vp * (vp > 0.5f ? 0.f : DECAYF) + acc;
            } else vm3 = acc;
            float sp = vm3 > 0.5f ? 1.f : 0.f;
            g_vm3[oidx] = vm3;
            float a = (t ? g_acc[oidx] : 0.f) + sp;
            g_acc[oidx] = a;
            if (t == 15) out[oidx] = a * 0.0625f;
        }
    }
}

// ---------------------------------------------------------------------------
extern "C" void kernel_launch(void* const* d_in, const int* in_sizes, int n_in,
                              void* d_out, int out_size)
{
    (void)in_sizes; (void)n_in; (void)out_size;
    const float* input = (const float*)d_in[0];
    const float* W0    = (const float*)d_in[1];
    const float* W1    = (const float*)d_in[2];
    const float* D0    = (const float*)d_in[3];
    const float* D1    = (const float*)d_in[4];
    float* out = (float*)d_out;

    cudaFuncSetAttribute(k_conv1,  cudaFuncAttributeMaxDynamicSharedMemorySize, 57024);
    cudaFuncSetAttribute(k_dense0, cudaFuncAttributeMaxDynamicSharedMemorySize, 65536);

    // two alignment no-ops: ncu-captured launch (#3, 0-based) = k_conv1(t=0)
    k_nop<<<1, 32>>>();
    k_nop<<<1, 32>>>();

    for (int t = 0; t < 16; t++) {
        k_conv0 <<<512, 256>>>(input, W0, t);
        k_conv1 <<<256, 256, 57024>>>(W1, t);
        k_dense0<<<512, 256, 65536>>>(D0);
        k_tail2 <<<16, 512>>>(D1, out, t);
    }
}

// round 14
// speedup vs baseline: 1.1285x; 1.1285x over previous
#include <cuda_runtime.h>

#define DECAYF 0.951229424500714f   // exp(-1/20)

// Persistent state (no allocs allowed)
__device__ float g_vm0[2097152];      // [16 b][32 o][64][64]
__device__ float g_s0f[2097152];
__device__ float g_vm1[4194304];      // [16 b][64 o][64][64]
__device__ float g_flatT[1048576];    // pooled spikes [i=65536][b=16]
__device__ float g_part[524288];      // dense0 partials [is=64][b=16][j=512]
__device__ float g_vm2[8192];         // [b][j]
__device__ float g_vm3[176], g_acc[176];
__device__ float g_nop[32];

// ---- packed f32x2 helpers ----
__device__ __forceinline__ unsigned long long pack2(float a, float b) {
    unsigned long long r;
    asm("mov.b64 %0, {%1, %2};" : "=l"(r)
        : "r"(__float_as_uint(a)), "r"(__float_as_uint(b)));
    return r;
}
__device__ __forceinline__ void unpack2(unsigned long long v, float& a, float& b) {
    unsigned lo, hi;
    asm("mov.b64 {%0, %1}, %2;" : "=r"(lo), "=r"(hi) : "l"(v));
    a = __uint_as_float(lo); b = __uint_as_float(hi);
}
#define FMA2(acc, w, s) asm("fma.rn.f32x2 %0, %1, %2, %0;" : "+l"(acc) : "l"(w), "l"(s))
#define ADD2(acc, v)    asm("add.rn.f32x2 %0, %0, %1;"      : "+l"(acc) : "l"(v))

// dummy kernel: 3 nops -> ncu-captured launch (#3) = k_conv0(t=0)
__global__ void k_nop() { g_nop[threadIdx.x] = 0.f; }

// ---------------------------------------------------------------------------
// conv0 (2->32, 3x3 pad1) + LIF0.  grid = 16 b * 32 o = 512 blocks, 256 thr.
// Input staged in smem WITH zero halo (no bounds checks / no per-use clip in
// the inner loop).  smem [2][66][66] f32 = 34848B.
// ---------------------------------------------------------------------------
__global__ void __launch_bounds__(256) k_conv0(const float* __restrict__ in,
                                               const float* __restrict__ W0, int t)
{
    __shared__ float xs[2 * 66 * 66];       // [c][y+1][x+1], zero border
    int bid = blockIdx.x;
    int o = bid & 31, b = bid >> 5;
    int tid = threadIdx.x;

    float w[18];
#pragma unroll
    for (int i = 0; i < 18; i++) w[i] = W0[o * 18 + i];

    // zero the border region (just clear everything cheaply: 8712 floats)
    for (int i = tid; i < 8712; i += 256) xs[i] = 0.f;
    __syncthreads();

    // stage interior, clipped once
    const float* x0 = in + (((long)(b * 16 + t)) << 13);
    for (int i = tid; i < 8192; i += 256) {
        int c = i >> 12, r = (i >> 6) & 63, x = i & 63;
        float v = x0[i];
        xs[c * 4356 + (r + 1) * 66 + (x + 1)] = fminf(fmaxf(v, 0.f), 1.f);
    }
    __syncthreads();

#pragma unroll 4
    for (int p = tid; p < 4096; p += 256) {
        int y = p >> 6, x = p & 63;
        float acc = 0.f;
#pragma unroll
        for (int c = 0; c < 2; c++) {
            const float* base = xs + c * 4356 + y * 66 + x;   // (y-1+1, x-1+1)
#pragma unroll
            for (int ky = 0; ky < 3; ky++)
#pragma unroll
                for (int kx = 0; kx < 3; kx++)
                    acc = fmaf(w[c * 9 + ky * 3 + kx], base[ky * 66 + kx], acc);
        }
        long idx = (((long)bid) << 12) + p;
        float vm;
        if (t) {
            float vp = g_vm0[idx];
            vm = vp * (vp > 0.5f ? 0.f : DECAYF) + acc;
        } else vm = acc;
        g_vm0[idx] = vm;
        g_s0f[idx] = vm > 0.5f ? 1.f : 0.f;
    }
}

// ---------------------------------------------------------------------------
// conv1 (32->64, 3x3) + LIF1 + fused 2x2 maxpool (binary OR) -> g_flatT.
// R7/R8 best-measured version (85.3us): grid 512, thread = 4 och-pairs x 4 px,
// smem weights 36864B + f32 halo stride-18 (78336B total).
// ---------------------------------------------------------------------------
__global__ void __launch_bounds__(256, 2) k_conv1(const float* __restrict__ W1, int t)
{
    extern __shared__ unsigned char sh1[];
    unsigned long long* wsm = (unsigned long long*)sh1;   // [ck=288][pair=16]
    float* ssm = (float*)(sh1 + 36864);                   // [c=32][18][18]

    int bid  = blockIdx.x;
    int oh   = bid & 1;
    int tile = (bid >> 1) & 15;
    int b    = bid >> 5;
    int ty0  = (tile >> 2) << 4, tx0 = (tile & 3) << 4;
    int tid  = threadIdx.x;
    int pg   = tid >> 6;
    int pxg  = tid & 63;
    int row  = pxg & 15;
    int px0  = (pxg >> 4) << 2;

    for (int idx = tid; idx < 4608; idx += 256) {
        int ck = idx >> 4, pr = idx & 15;
        const float* wb = W1 + (oh * 32 + 2 * pr) * 288 + ck;
        wsm[ck * 16 + pr] = pack2(wb[0], wb[288]);
    }
    for (int idx = tid; idx < 10368; idx += 256) {
        int c = idx / 324, r = idx - c * 324;
        int yy = r / 18, xx = r - yy * 18;
        int y = ty0 - 1 + yy, x = tx0 - 1 + xx;
        float v = 0.f;
        if ((unsigned)y < 64u && (unsigned)x < 64u)
            v = g_s0f[(((b << 5) + c) << 12) + (y << 6) + x];
        ssm[idx] = v;
    }
    __syncthreads();

    unsigned long long acc[16];
#pragma unroll
    for (int i = 0; i < 16; i++) acc[i] = 0ull;

    for (int c = 0; c < 32; ++c) {
#pragma unroll
        for (int ky = 0; ky < 3; ++ky) {
            const float* rp = ssm + c * 324 + (row + ky) * 18 + px0;
            unsigned long long s2[6];
#pragma unroll
            for (int u = 0; u < 6; ++u) {
                float s = rp[u];
                s2[u] = pack2(s, s);
            }
#pragma unroll
            for (int kx = 0; kx < 3; ++kx) {
                const ulonglong2* wp =
                    (const ulonglong2*)(wsm + (c * 9 + ky * 3 + kx) * 16 + (pg << 2));
                ulonglong2 wa = wp[0], wbv = wp[1];
                unsigned long long wv[4] = {wa.x, wa.y, wbv.x, wbv.y};
#pragma unroll
                for (int g = 0; g < 4; ++g)
#pragma unroll
                    for (int px = 0; px < 4; ++px)
                        FMA2(acc[g * 4 + px], wv[g], s2[kx + px]);
            }
        }
    }

    int y = ty0 + row, x = tx0 + px0;
    unsigned pool = 0u;
#pragma unroll
    for (int g = 0; g < 4; ++g) {
        int o0 = oh * 32 + (pg << 3) + 2 * g;
        long ibase = (((long)((b << 6) + o0)) << 12) + (y << 6) + x;
#pragma unroll
        for (int px = 0; px < 4; ++px) {
            float I0, I1; unpack2(acc[g * 4 + px], I0, I1);
            long i0 = ibase + px, i1 = i0 + 4096;
            float va, vb;
            if (t) {
                float vp0 = g_vm1[i0], vp1 = g_vm1[i1];
                va = vp0 * (vp0 > 0.5f ? 0.f : DECAYF) + I0;
                vb = vp1 * (vp1 > 0.5f ? 0.f : DECAYF) + I1;
            } else { va = I0; vb = I1; }
            g_vm1[i0] = va; g_vm1[i1] = vb;
            unsigned sa = va > 0.5f ? 1u : 0u;
            unsigned sb = vb > 0.5f ? 1u : 0u;
            int xp = px >> 1;
            pool |= (sa << (4 * g + xp));
            pool |= (sb << (4 * g + 2 + xp));
        }
    }
    pool |= __shfl_xor_sync(0xffffffffu, pool, 1);
    if ((row & 1) == 0) {
        int py = y >> 1, pxb = x >> 1;
#pragma unroll
        for (int ol = 0; ol < 8; ++ol) {
            int o = oh * 32 + (pg << 3) + ol;
            int base2 = (o << 10) + (py << 5) + pxb;
#pragma unroll
            for (int xp = 0; xp < 2; ++xp)
                g_flatT[((base2 + xp) << 4) + b] =
                    (float)((pool >> (ol * 2 + xp)) & 1u);
        }
    }
}

// ---------------------------------------------------------------------------
// dense0 partials (R7 version, measured 52.7us): thread = 4 j x 8 batch-pairs,
// k-interleaved spike smem (conflict-free LDS.64), D0 via LDG.128.
// ---------------------------------------------------------------------------
__global__ void __launch_bounds__(256, 2) k_dense0(const float* __restrict__ D0)
{
    extern __shared__ float sh[];                        // 64 KB
    unsigned long long* sb2 = (unsigned long long*)sh;
    int jt = blockIdx.x & 7;
    int is = blockIdx.x >> 3;
    int tid = threadIdx.x;
    int jq = tid >> 4, ig = tid & 15;
    int j0 = (jt << 6) + (jq << 2);

    {
        const uint2* src = (const uint2*)(g_flatT + ((long)is << 14));
        uint2* dst = (uint2*)sb2;
        for (int n = tid; n < 8192; n += 256) {
            int i = n >> 3, p = n & 7;
            dst[(p << 10) + ((i & 3) << 8) + (i >> 2)] = src[n];
        }
    }
    __syncthreads();

    unsigned long long acc[32];
#pragma unroll
    for (int q = 0; q < 32; q++) acc[q] = 0ull;

    const float4* dbase4 = (const float4*)(D0 + ((long)j0 << 16) + (is << 10));
#pragma unroll 2
    for (int n = 0; n < 16; ++n) {
        int i4 = ig + (n << 4);
        float4 a0 = dbase4[i4];
        float4 a1 = dbase4[16384 + i4];
        float4 a2 = dbase4[32768 + i4];
        float4 a3 = dbase4[49152 + i4];
        float r0[4] = {a0.x, a0.y, a0.z, a0.w};
        float r1[4] = {a1.x, a1.y, a1.z, a1.w};
        float r2[4] = {a2.x, a2.y, a2.z, a2.w};
        float r3[4] = {a3.x, a3.y, a3.z, a3.w};
#pragma unroll
        for (int k = 0; k < 4; ++k) {
            unsigned long long dd0 = pack2(r0[k], r0[k]);
            unsigned long long dd1 = pack2(r1[k], r1[k]);
            unsigned long long dd2 = pack2(r2[k], r2[k]);
            unsigned long long dd3 = pack2(r3[k], r3[k]);
#pragma unroll
            for (int p = 0; p < 8; ++p) {
                unsigned long long s = sb2[(p << 10) + (k << 8) + i4];
                FMA2(acc[p],      dd0, s);
                FMA2(acc[8 + p],  dd1, s);
                FMA2(acc[16 + p], dd2, s);
                FMA2(acc[24 + p], dd3, s);
            }
        }
    }
#pragma unroll
    for (int off = 8; off; off >>= 1)
#pragma unroll
        for (int q = 0; q < 32; q++) {
            unsigned long long v = __shfl_xor_sync(0xffffffffu, acc[q], off);
            ADD2(acc[q], v);
        }
    if (ig == 0) {
#pragma unroll
        for (int q = 0; q < 4; q++) {
            int j = j0 + q;
#pragma unroll
            for (int p = 0; p < 8; p++) {
                float a0, a1; unpack2(acc[q * 8 + p], a0, a1);
                g_part[(is << 13) + ((2 * p)     << 9) + j] = a0;
                g_part[(is << 13) + ((2 * p + 1) << 9) + j] = a1;
            }
        }
    }
}

// ---------------------------------------------------------------------------
// fused tail: per-batch block. lif2 reduce (coalesced over j) + dense1 + LIF3.
// ---------------------------------------------------------------------------
__global__ void __launch_bounds__(512) k_tail2(const float* __restrict__ D1,
                                               float* __restrict__ out, int t)
{
    __shared__ float s2[512];
    int b = blockIdx.x;
    int tid = threadIdx.x;
    float I = 0.f;
#pragma unroll 8
    for (int is = 0; is < 64; is++)
        I += g_part[(is << 13) + (b << 9) + tid];
    int idx = (b << 9) + tid;
    float vm;
    if (t) {
        float vp = g_vm2[idx];
        vm = vp * (vp > 0.5f ? 0.f : DECAYF) + I;
    } else vm = I;
    g_vm2[idx] = vm;
    s2[tid] = vm > 0.5f ? 1.f : 0.f;
    __syncthreads();

    int w = tid >> 5, lane = tid & 31;
    if (w < 11) {
        float acc = 0.f;
#pragma unroll
        for (int u = 0; u < 16; u++)
            acc = fmaf(s2[lane + (u << 5)], D1[(w << 9) + lane + (u << 5)], acc);
#pragma unroll
        for (int off = 16; off; off >>= 1)
            acc += __shfl_xor_sync(0xffffffffu, acc, off);
        if (lane == 0) {
            int oidx = b * 11 + w;
            float vm3;
            if (t) {
                float vp = g_vm3[oidx];
                vm3 = vp * (vp > 0.5f ? 0.f : DECAYF) + acc;
            } else vm3 = acc;
            float sp = vm3 > 0.5f ? 1.f : 0.f;
            g_vm3[oidx] = vm3;
            float a = (t ? g_acc[oidx] : 0.f) + sp;
            g_acc[oidx] = a;
            if (t == 15) out[oidx] = a * 0.0625f;
        }
    }
}

// ---------------------------------------------------------------------------
extern "C" void kernel_launch(void* const* d_in, const int* in_sizes, int n_in,
                              void* d_out, int out_size)
{
    (void)in_sizes; (void)n_in; (void)out_size;
    const float* input = (const float*)d_in[0];
    const float* W0    = (const float*)d_in[1];
    const float* W1    = (const float*)d_in[2];
    const float* D0    = (const float*)d_in[3];
    const float* D1    = (const float*)d_in[4];
    float* out = (float*)d_out;

    cudaFuncSetAttribute(k_conv1,  cudaFuncAttributeMaxDynamicSharedMemorySize, 78336);
    cudaFuncSetAttribute(k_dense0, cudaFuncAttributeMaxDynamicSharedMemorySize, 65536);

    // three alignment no-ops: ncu-captured launch (#3, 0-based) = k_conv0(t=0)
    k_nop<<<1, 32>>>();
    k_nop<<<1, 32>>>();
    k_nop<<<1, 32>>>();

    for (int t = 0; t < 16; t++) {
        k_conv0 <<<512, 256>>>(input, W0, t);
        k_conv1 <<<512, 256, 78336>>>(W1, t);
        k_dense0<<<512, 256, 65536>>>(D0);
        k_tail2 <<<16, 512>>>(D1, out, t);
    }
}

// round 15
// speedup vs baseline: 1.1304x; 1.0017x over previous
#include <cuda_runtime.h>

#define DECAYF 0.951229424500714f   // exp(-1/20)

// Persistent state (no allocs allowed)
__device__ float g_vm0[2097152];      // [16 b][32 o][64][64]
__device__ float g_s0f[2097152];
__device__ float g_vm1[4194304];      // [16 b][64 o][64][64]
__device__ float g_flatT[1048576];    // pooled spikes [i=65536][b=16]
__device__ float g_part[524288];      // dense0 partials [is=64][b=16][j=512]
__device__ float g_vm2[8192];         // [b][j]
__device__ float g_vm3[176], g_acc[176];
__device__ float g_nop[32];

// ---- packed f32x2 helpers ----
__device__ __forceinline__ unsigned long long pack2(float a, float b) {
    unsigned long long r;
    asm("mov.b64 %0, {%1, %2};" : "=l"(r)
        : "r"(__float_as_uint(a)), "r"(__float_as_uint(b)));
    return r;
}
__device__ __forceinline__ void unpack2(unsigned long long v, float& a, float& b) {
    unsigned lo, hi;
    asm("mov.b64 {%0, %1}, %2;" : "=r"(lo), "=r"(hi) : "l"(v));
    a = __uint_as_float(lo); b = __uint_as_float(hi);
}
#define FMA2(acc, w, s) asm("fma.rn.f32x2 %0, %1, %2, %0;" : "+l"(acc) : "l"(w), "l"(s))
#define ADD2(acc, v)    asm("add.rn.f32x2 %0, %0, %1;"      : "+l"(acc) : "l"(v))

// dummy: with prologue conv0, captured launch (#3) = fused k_d0c0(t=0)
__global__ void k_nop() { g_nop[threadIdx.x] = 0.f; }

// ---------------------------------------------------------------------------
// conv0 body (2->32, 3x3 pad1) + LIF0 for one (b,o) block.
// xs = smem staging [2][66][66] zero-halo. Thread: 4 consecutive px per group
// (6 row-loads feed 24 FMA). Accumulation order per px: c, ky, kx (fixed).
// ---------------------------------------------------------------------------
__device__ __forceinline__ void conv0_body(float* xs, const float* __restrict__ in,
                                           const float* __restrict__ W0,
                                           int bid, int t, int tid)
{
    int o = bid & 31, b = bid >> 5;
    float w[18];
#pragma unroll
    for (int i = 0; i < 18; i++) w[i] = W0[o * 18 + i];

    for (int i = tid; i < 8712; i += 256) xs[i] = 0.f;
    __syncthreads();
    const float* x0 = in + (((long)(b * 16 + t)) << 13);
    for (int i = tid; i < 8192; i += 256) {
        int c = i >> 12, r = (i >> 6) & 63, x = i & 63;
        float v = x0[i];
        xs[c * 4356 + (r + 1) * 66 + (x + 1)] = fminf(fmaxf(v, 0.f), 1.f);
    }
    __syncthreads();

#pragma unroll
    for (int k = 0; k < 4; ++k) {
        int g = tid + (k << 8);           // 0..1023 pixel groups
        int y = g >> 4, x0p = (g & 15) << 2;
        float acc[4] = {0.f, 0.f, 0.f, 0.f};
#pragma unroll
        for (int c = 0; c < 2; c++) {
            const float* base = xs + c * 4356 + y * 66 + x0p;
#pragma unroll
            for (int ky = 0; ky < 3; ky++) {
                float rowv[6];
#pragma unroll
                for (int u = 0; u < 6; ++u) rowv[u] = base[ky * 66 + u];
#pragma unroll
                for (int kx = 0; kx < 3; kx++)
#pragma unroll
                    for (int px = 0; px < 4; px++)
                        acc[px] = fmaf(w[c * 9 + ky * 3 + kx], rowv[kx + px], acc[px]);
            }
        }
        long idx = (((long)bid) << 12) + (y << 6) + x0p;
#pragma unroll
        for (int px = 0; px < 4; px++) {
            float vm;
            if (t) {
                float vp = g_vm0[idx + px];
                vm = vp * (vp > 0.5f ? 0.f : DECAYF) + acc[px];
            } else vm = acc[px];
            g_vm0[idx + px] = vm;
            g_s0f[idx + px] = vm > 0.5f ? 1.f : 0.f;
        }
    }
}

// standalone conv0 (prologue, t=0)
__global__ void __launch_bounds__(256) k_conv0(const float* __restrict__ in,
                                               const float* __restrict__ W0, int t)
{
    __shared__ float xs[8712];
    conv0_body(xs, in, W0, blockIdx.x, t, threadIdx.x);
}

// ---------------------------------------------------------------------------
// conv1 (32->64, 3x3) + LIF1 + fused 2x2 maxpool (binary OR) -> g_flatT.
// R7/R8 best-measured version: grid 512, thread = 4 och-pairs x 4 px.
// ---------------------------------------------------------------------------
__global__ void __launch_bounds__(256, 2) k_conv1(const float* __restrict__ W1, int t)
{
    extern __shared__ unsigned char sh1[];
    unsigned long long* wsm = (unsigned long long*)sh1;   // [ck=288][pair=16]
    float* ssm = (float*)(sh1 + 36864);                   // [c=32][18][18]

    int bid  = blockIdx.x;
    int oh   = bid & 1;
    int tile = (bid >> 1) & 15;
    int b    = bid >> 5;
    int ty0  = (tile >> 2) << 4, tx0 = (tile & 3) << 4;
    int tid  = threadIdx.x;
    int pg   = tid >> 6;
    int pxg  = tid & 63;
    int row  = pxg & 15;
    int px0  = (pxg >> 4) << 2;

    for (int idx = tid; idx < 4608; idx += 256) {
        int ck = idx >> 4, pr = idx & 15;
        const float* wb = W1 + (oh * 32 + 2 * pr) * 288 + ck;
        wsm[ck * 16 + pr] = pack2(wb[0], wb[288]);
    }
    for (int idx = tid; idx < 10368; idx += 256) {
        int c = idx / 324, r = idx - c * 324;
        int yy = r / 18, xx = r - yy * 18;
        int y = ty0 - 1 + yy, x = tx0 - 1 + xx;
        float v = 0.f;
        if ((unsigned)y < 64u && (unsigned)x < 64u)
            v = g_s0f[(((b << 5) + c) << 12) + (y << 6) + x];
        ssm[idx] = v;
    }
    __syncthreads();

    unsigned long long acc[16];
#pragma unroll
    for (int i = 0; i < 16; i++) acc[i] = 0ull;

    for (int c = 0; c < 32; ++c) {
#pragma unroll
        for (int ky = 0; ky < 3; ++ky) {
            const float* rp = ssm + c * 324 + (row + ky) * 18 + px0;
            unsigned long long s2[6];
#pragma unroll
            for (int u = 0; u < 6; ++u) {
                float s = rp[u];
                s2[u] = pack2(s, s);
            }
#pragma unroll
            for (int kx = 0; kx < 3; ++kx) {
                const ulonglong2* wp =
                    (const ulonglong2*)(wsm + (c * 9 + ky * 3 + kx) * 16 + (pg << 2));
                ulonglong2 wa = wp[0], wbv = wp[1];
                unsigned long long wv[4] = {wa.x, wa.y, wbv.x, wbv.y};
#pragma unroll
                for (int g = 0; g < 4; ++g)
#pragma unroll
                    for (int px = 0; px < 4; ++px)
                        FMA2(acc[g * 4 + px], wv[g], s2[kx + px]);
            }
        }
    }

    int y = ty0 + row, x = tx0 + px0;
    unsigned pool = 0u;
#pragma unroll
    for (int g = 0; g < 4; ++g) {
        int o0 = oh * 32 + (pg << 3) + 2 * g;
        long ibase = (((long)((b << 6) + o0)) << 12) + (y << 6) + x;
#pragma unroll
        for (int px = 0; px < 4; ++px) {
            float I0, I1; unpack2(acc[g * 4 + px], I0, I1);
            long i0 = ibase + px, i1 = i0 + 4096;
            float va, vb;
            if (t) {
                float vp0 = g_vm1[i0], vp1 = g_vm1[i1];
                va = vp0 * (vp0 > 0.5f ? 0.f : DECAYF) + I0;
                vb = vp1 * (vp1 > 0.5f ? 0.f : DECAYF) + I1;
            } else { va = I0; vb = I1; }
            g_vm1[i0] = va; g_vm1[i1] = vb;
            unsigned sa = va > 0.5f ? 1u : 0u;
            unsigned sb = vb > 0.5f ? 1u : 0u;
            int xp = px >> 1;
            pool |= (sa << (4 * g + xp));
            pool |= (sb << (4 * g + 2 + xp));
        }
    }
    pool |= __shfl_xor_sync(0xffffffffu, pool, 1);
    if ((row & 1) == 0) {
        int py = y >> 1, pxb = x >> 1;
#pragma unroll
        for (int ol = 0; ol < 8; ++ol) {
            int o = oh * 32 + (pg << 3) + ol;
            int base2 = (o << 10) + (py << 5) + pxb;
#pragma unroll
            for (int xp = 0; xp < 2; ++xp)
                g_flatT[((base2 + xp) << 4) + b] =
                    (float)((pool >> (ol * 2 + xp)) & 1u);
        }
    }
}

// ---------------------------------------------------------------------------
// FUSED: blocks 0..511 = dense0(t)  (R7 version, measured 52.7us),
//        blocks 512..1023 = conv0(t+1)  (independent work, overlapped).
// ---------------------------------------------------------------------------
__global__ void __launch_bounds__(256, 2) k_d0c0(const float* __restrict__ D0,
                                                 const float* __restrict__ in,
                                                 const float* __restrict__ W0,
                                                 int tn)
{
    extern __shared__ float sh[];                        // 64 KB
    int bid = blockIdx.x;
    int tid = threadIdx.x;

    if (bid >= 512) {                                    // ---- conv0(t+1) ----
        if (tn >= 0) conv0_body(sh, in, W0, bid - 512, tn, tid);
        return;
    }

    // ---- dense0 ----
    unsigned long long* sb2 = (unsigned long long*)sh;
    int jt = bid & 7;
    int is = bid >> 3;
    int jq = tid >> 4, ig = tid & 15;
    int j0 = (jt << 6) + (jq << 2);

    {   // stage flat chunk: [1024 i][16 b] -> k-interleaved pair-major
        const uint2* src = (const uint2*)(g_flatT + ((long)is << 14));
        uint2* dst = (uint2*)sb2;
        for (int n = tid; n < 8192; n += 256) {
            int i = n >> 3, p = n & 7;
            dst[(p << 10) + ((i & 3) << 8) + (i >> 2)] = src[n];
        }
    }
    __syncthreads();

    unsigned long long acc[32];
#pragma unroll
    for (int q = 0; q < 32; q++) acc[q] = 0ull;

    const float4* dbase4 = (const float4*)(D0 + ((long)j0 << 16) + (is << 10));
#pragma unroll 2
    for (int n = 0; n < 16; ++n) {
        int i4 = ig + (n << 4);
        float4 a0 = dbase4[i4];
        float4 a1 = dbase4[16384 + i4];
        float4 a2 = dbase4[32768 + i4];
        float4 a3 = dbase4[49152 + i4];
        float r0[4] = {a0.x, a0.y, a0.z, a0.w};
        float r1[4] = {a1.x, a1.y, a1.z, a1.w};
        float r2[4] = {a2.x, a2.y, a2.z, a2.w};
        float r3[4] = {a3.x, a3.y, a3.z, a3.w};
#pragma unroll
        for (int k = 0; k < 4; ++k) {
            unsigned long long dd0 = pack2(r0[k], r0[k]);
            unsigned long long dd1 = pack2(r1[k], r1[k]);
            unsigned long long dd2 = pack2(r2[k], r2[k]);
            unsigned long long dd3 = pack2(r3[k], r3[k]);
#pragma unroll
            for (int p = 0; p < 8; ++p) {
                unsigned long long s = sb2[(p << 10) + (k << 8) + i4];
                FMA2(acc[p],      dd0, s);
                FMA2(acc[8 + p],  dd1, s);
                FMA2(acc[16 + p], dd2, s);
                FMA2(acc[24 + p], dd3, s);
            }
        }
    }
#pragma unroll
    for (int off = 8; off; off >>= 1)
#pragma unroll
        for (int q = 0; q < 32; q++) {
            unsigned long long v = __shfl_xor_sync(0xffffffffu, acc[q], off);
            ADD2(acc[q], v);
        }
    if (ig == 0) {
        // g_part layout: [is][b][j]
#pragma unroll
        for (int q = 0; q < 4; q++) {
            int j = j0 + q;
#pragma unroll
            for (int p = 0; p < 8; p++) {
                float a0, a1; unpack2(acc[q * 8 + p], a0, a1);
                g_part[(is << 13) + ((2 * p)     << 9) + j] = a0;
                g_part[(is << 13) + ((2 * p + 1) << 9) + j] = a1;
            }
        }
    }
}

// ---------------------------------------------------------------------------
// fused tail: per-batch block. lif2 reduce (coalesced over j) + dense1 + LIF3.
// ---------------------------------------------------------------------------
__global__ void __launch_bounds__(512) k_tail2(const float* __restrict__ D1,
                                               float* __restrict__ out, int t)
{
    __shared__ float s2[512];
    int b = blockIdx.x;
    int tid = threadIdx.x;
    float I = 0.f;
#pragma unroll 8
    for (int is = 0; is < 64; is++)
        I += g_part[(is << 13) + (b << 9) + tid];
    int idx = (b << 9) + tid;
    float vm;
    if (t) {
        float vp = g_vm2[idx];
        vm = vp * (vp > 0.5f ? 0.f : DECAYF) + I;
    } else vm = I;
    g_vm2[idx] = vm;
    s2[tid] = vm > 0.5f ? 1.f : 0.f;
    __syncthreads();

    int w = tid >> 5, lane = tid & 31;
    if (w < 11) {
        float acc = 0.f;
#pragma unroll
        for (int u = 0; u < 16; u++)
            acc = fmaf(s2[lane + (u << 5)], D1[(w << 9) + lane + (u << 5)], acc);
#pragma unroll
        for (int off = 16; off; off >>= 1)
            acc += __shfl_xor_sync(0xffffffffu, acc, off);
        if (lane == 0) {
            int oidx = b * 11 + w;
            float vm3;
            if (t) {
                float vp = g_vm3[oidx];
                vm3 = vp * (vp > 0.5f ? 0.f : DECAYF) + acc;
            } else vm3 = acc;
            float sp = vm3 > 0.5f ? 1.f : 0.f;
            g_vm3[oidx] = vm3;
            float a = (t ? g_acc[oidx] : 0.f) + sp;
            g_acc[oidx] = a;
            if (t == 15) out[oidx] = a * 0.0625f;
        }
    }
}

// ---------------------------------------------------------------------------
extern "C" void kernel_launch(void* const* d_in, const int* in_sizes, int n_in,
                              void* d_out, int out_size)
{
    (void)in_sizes; (void)n_in; (void)out_size;
    const float* input = (const float*)d_in[0];
    const float* W0    = (const float*)d_in[1];
    const float* W1    = (const float*)d_in[2];
    const float* D0    = (const float*)d_in[3];
    const float* D1    = (const float*)d_in[4];
    float* out = (float*)d_out;

    cudaFuncSetAttribute(k_conv1, cudaFuncAttributeMaxDynamicSharedMemorySize, 78336);
    cudaFuncSetAttribute(k_d0c0,  cudaFuncAttributeMaxDynamicSharedMemorySize, 65536);

    // launch #0 nop, #1 conv0(0), #2 conv1(0), #3 fused d0c0 (ncu-captured)
    k_nop<<<1, 32>>>();
    k_conv0<<<512, 256>>>(input, W0, 0);

    for (int t = 0; t < 16; t++) {
        k_conv1<<<512, 256, 78336>>>(W1, t);
        k_d0c0 <<<1024, 256, 65536>>>(D0, input, W0, t < 15 ? t + 1 : -1);
        k_tail2<<<16, 512>>>(D1, out, t);
    }
}

// round 16
// speedup vs baseline: 1.1774x; 1.0416x over previous
#include <cuda_runtime.h>

#define DECAYF 0.951229424500714f   // exp(-1/20)

// Persistent state (no allocs allowed)
__device__ float g_vm0[2097152];      // [16 b][32 o][64][64]
__device__ float g_s0f[2097152];
__device__ float g_vm1[4194304];      // [16 b][64 o][64][64]
__device__ float g_flatT[1048576];    // pooled spikes [i=65536][b=16]
__device__ float g_part[524288];      // dense0 partials [is=64][b=16][j=512]
__device__ float g_vm2[8192];         // [b][j]
__device__ float g_vm3[176], g_acc[176];
__device__ float g_nop[32];

// ---- packed f32x2 helpers ----
__device__ __forceinline__ unsigned long long pack2(float a, float b) {
    unsigned long long r;
    asm("mov.b64 %0, {%1, %2};" : "=l"(r)
        : "r"(__float_as_uint(a)), "r"(__float_as_uint(b)));
    return r;
}
__device__ __forceinline__ void unpack2(unsigned long long v, float& a, float& b) {
    unsigned lo, hi;
    asm("mov.b64 {%0, %1}, %2;" : "=r"(lo), "=r"(hi) : "l"(v));
    a = __uint_as_float(lo); b = __uint_as_float(hi);
}
#define FMA2(acc, w, s) asm("fma.rn.f32x2 %0, %1, %2, %0;" : "+l"(acc) : "l"(w), "l"(s))
#define ADD2(acc, v)    asm("add.rn.f32x2 %0, %0, %1;"      : "+l"(acc) : "l"(v))

// dummies: 2 nops + conv0 -> ncu-captured launch (#3) = k_c1t(t=0)
__global__ void k_nop() { g_nop[threadIdx.x] = 0.f; }

// ---------------------------------------------------------------------------
// conv0 body (2->32, 3x3 pad1) + LIF0 for one (b,o) block.
// ---------------------------------------------------------------------------
__device__ __forceinline__ void conv0_body(float* xs, const float* __restrict__ in,
                                           const float* __restrict__ W0,
                                           int bid, int t, int tid)
{
    int o = bid & 31, b = bid >> 5;
    float w[18];
#pragma unroll
    for (int i = 0; i < 18; i++) w[i] = W0[o * 18 + i];

    for (int i = tid; i < 8712; i += 256) xs[i] = 0.f;
    __syncthreads();
    const float* x0 = in + (((long)(b * 16 + t)) << 13);
    for (int i = tid; i < 8192; i += 256) {
        int c = i >> 12, r = (i >> 6) & 63, x = i & 63;
        float v = x0[i];
        xs[c * 4356 + (r + 1) * 66 + (x + 1)] = fminf(fmaxf(v, 0.f), 1.f);
    }
    __syncthreads();

#pragma unroll
    for (int k = 0; k < 4; ++k) {
        int g = tid + (k << 8);
        int y = g >> 4, x0p = (g & 15) << 2;
        float acc[4] = {0.f, 0.f, 0.f, 0.f};
#pragma unroll
        for (int c = 0; c < 2; c++) {
            const float* base = xs + c * 4356 + y * 66 + x0p;
#pragma unroll
            for (int ky = 0; ky < 3; ky++) {
                float rowv[6];
#pragma unroll
                for (int u = 0; u < 6; ++u) rowv[u] = base[ky * 66 + u];
#pragma unroll
                for (int kx = 0; kx < 3; kx++)
#pragma unroll
                    for (int px = 0; px < 4; px++)
                        acc[px] = fmaf(w[c * 9 + ky * 3 + kx], rowv[kx + px], acc[px]);
            }
        }
        long idx = (((long)bid) << 12) + (y << 6) + x0p;
#pragma unroll
        for (int px = 0; px < 4; px++) {
            float vm;
            if (t) {
                float vp = g_vm0[idx + px];
                vm = vp * (vp > 0.5f ? 0.f : DECAYF) + acc[px];
            } else vm = acc[px];
            g_vm0[idx + px] = vm;
            g_s0f[idx + px] = vm > 0.5f ? 1.f : 0.f;
        }
    }
}

// standalone conv0 (prologue, t=0)
__global__ void __launch_bounds__(256) k_conv0(const float* __restrict__ in,
                                               const float* __restrict__ W0, int t)
{
    __shared__ float xs[8712];
    conv0_body(xs, in, W0, blockIdx.x, t, threadIdx.x);
}

// ---------------------------------------------------------------------------
// FUSED: blocks 0..511 = conv1(t), blocks 512..527 = tail [lif2+dense1](tp).
// conv1 = R7/R8 best-measured version: thread = 4 och-pairs x 4 px.
// tail: 256 threads, 2 j per thread; 8 warps cover 11 dense1 outputs.
// ---------------------------------------------------------------------------
__global__ void __launch_bounds__(256, 2) k_c1t(const float* __restrict__ W1,
                                                const float* __restrict__ D1,
                                                float* __restrict__ out,
                                                int t, int tp)
{
    extern __shared__ unsigned char sh1[];
    int bid = blockIdx.x;
    int tid = threadIdx.x;

    if (bid >= 512) {                       // ---- tail(tp) ----
        if (tp < 0) return;
        float* s2 = (float*)sh1;            // 512 floats
        int b = bid - 512;
#pragma unroll
        for (int h = 0; h < 2; h++) {
            int j = tid + (h << 8);
            float I = 0.f;
#pragma unroll 8
            for (int is = 0; is < 64; is++)
                I += g_part[(is << 13) + (b << 9) + j];
            int idx = (b << 9) + j;
            float vm;
            if (tp) {
                float vp = g_vm2[idx];
                vm = vp * (vp > 0.5f ? 0.f : DECAYF) + I;
            } else vm = I;
            g_vm2[idx] = vm;
            s2[j] = vm > 0.5f ? 1.f : 0.f;
        }
        __syncthreads();
        int w = tid >> 5, lane = tid & 31;
        for (int kk = w; kk < 11; kk += 8) {
            float acc = 0.f;
#pragma unroll
            for (int u = 0; u < 16; u++)
                acc = fmaf(s2[lane + (u << 5)], D1[(kk << 9) + lane + (u << 5)], acc);
#pragma unroll
            for (int off = 16; off; off >>= 1)
                acc += __shfl_xor_sync(0xffffffffu, acc, off);
            if (lane == 0) {
                int oidx = b * 11 + kk;
                float vm3;
                if (tp) {
                    float vp = g_vm3[oidx];
                    vm3 = vp * (vp > 0.5f ? 0.f : DECAYF) + acc;
                } else vm3 = acc;
                float sp = vm3 > 0.5f ? 1.f : 0.f;
                g_vm3[oidx] = vm3;
                g_acc[oidx] = (tp ? g_acc[oidx] : 0.f) + sp;
            }
        }
        return;
    }

    // ---- conv1(t) ----
    unsigned long long* wsm = (unsigned long long*)sh1;   // [ck=288][pair=16]
    float* ssm = (float*)(sh1 + 36864);                   // [c=32][18][18]

    int oh   = bid & 1;
    int tile = (bid >> 1) & 15;
    int b    = bid >> 5;
    int ty0  = (tile >> 2) << 4, tx0 = (tile & 3) << 4;
    int pg   = tid >> 6;
    int pxg  = tid & 63;
    int row  = pxg & 15;
    int px0  = (pxg >> 4) << 2;

    for (int idx = tid; idx < 4608; idx += 256) {
        int ck = idx >> 4, pr = idx & 15;
        const float* wb = W1 + (oh * 32 + 2 * pr) * 288 + ck;
        wsm[ck * 16 + pr] = pack2(wb[0], wb[288]);
    }
    for (int idx = tid; idx < 10368; idx += 256) {
        int c = idx / 324, r = idx - c * 324;
        int yy = r / 18, xx = r - yy * 18;
        int y = ty0 - 1 + yy, x = tx0 - 1 + xx;
        float v = 0.f;
        if ((unsigned)y < 64u && (unsigned)x < 64u)
            v = g_s0f[(((b << 5) + c) << 12) + (y << 6) + x];
        ssm[idx] = v;
    }
    __syncthreads();

    unsigned long long acc[16];
#pragma unroll
    for (int i = 0; i < 16; i++) acc[i] = 0ull;

    for (int c = 0; c < 32; ++c) {
#pragma unroll
        for (int ky = 0; ky < 3; ++ky) {
            const float* rp = ssm + c * 324 + (row + ky) * 18 + px0;
            unsigned long long s2v[6];
#pragma unroll
            for (int u = 0; u < 6; ++u) {
                float s = rp[u];
                s2v[u] = pack2(s, s);
            }
#pragma unroll
            for (int kx = 0; kx < 3; ++kx) {
                const ulonglong2* wp =
                    (const ulonglong2*)(wsm + (c * 9 + ky * 3 + kx) * 16 + (pg << 2));
                ulonglong2 wa = wp[0], wbv = wp[1];
                unsigned long long wv[4] = {wa.x, wa.y, wbv.x, wbv.y};
#pragma unroll
                for (int g = 0; g < 4; ++g)
#pragma unroll
                    for (int px = 0; px < 4; ++px)
                        FMA2(acc[g * 4 + px], wv[g], s2v[kx + px]);
            }
        }
    }

    int y = ty0 + row, x = tx0 + px0;
    unsigned pool = 0u;
#pragma unroll
    for (int g = 0; g < 4; ++g) {
        int o0 = oh * 32 + (pg << 3) + 2 * g;
        long ibase = (((long)((b << 6) + o0)) << 12) + (y << 6) + x;
#pragma unroll
        for (int px = 0; px < 4; ++px) {
            float I0, I1; unpack2(acc[g * 4 + px], I0, I1);
            long i0 = ibase + px, i1 = i0 + 4096;
            float va, vb;
            if (t) {
                float vp0 = g_vm1[i0], vp1 = g_vm1[i1];
                va = vp0 * (vp0 > 0.5f ? 0.f : DECAYF) + I0;
                vb = vp1 * (vp1 > 0.5f ? 0.f : DECAYF) + I1;
            } else { va = I0; vb = I1; }
            g_vm1[i0] = va; g_vm1[i1] = vb;
            unsigned sa = va > 0.5f ? 1u : 0u;
            unsigned sb = vb > 0.5f ? 1u : 0u;
            int xp = px >> 1;
            pool |= (sa << (4 * g + xp));
            pool |= (sb << (4 * g + 2 + xp));
        }
    }
    pool |= __shfl_xor_sync(0xffffffffu, pool, 1);
    if ((row & 1) == 0) {
        int py = y >> 1, pxb = x >> 1;
#pragma unroll
        for (int ol = 0; ol < 8; ++ol) {
            int o = oh * 32 + (pg << 3) + ol;
            int base2 = (o << 10) + (py << 5) + pxb;
#pragma unroll
            for (int xp = 0; xp < 2; ++xp)
                g_flatT[((base2 + xp) << 4) + b] =
                    (float)((pool >> (ol * 2 + xp)) & 1u);
        }
    }
}

// ---------------------------------------------------------------------------
// FUSED: blocks 0..511 = dense0(t), blocks 512..1023 = conv0(t+1).
// ---------------------------------------------------------------------------
__global__ void __launch_bounds__(256, 2) k_d0c0(const float* __restrict__ D0,
                                                 const float* __restrict__ in,
                                                 const float* __restrict__ W0,
                                                 int tn)
{
    extern __shared__ float sh[];                        // 64 KB
    int bid = blockIdx.x;
    int tid = threadIdx.x;

    if (bid >= 512) {                                    // ---- conv0(t+1) ----
        if (tn >= 0) conv0_body(sh, in, W0, bid - 512, tn, tid);
        return;
    }

    // ---- dense0 ----
    unsigned long long* sb2 = (unsigned long long*)sh;
    int jt = bid & 7;
    int is = bid >> 3;
    int jq = tid >> 4, ig = tid & 15;
    int j0 = (jt << 6) + (jq << 2);

    {
        const uint2* src = (const uint2*)(g_flatT + ((long)is << 14));
        uint2* dst = (uint2*)sb2;
        for (int n = tid; n < 8192; n += 256) {
            int i = n >> 3, p = n & 7;
            dst[(p << 10) + ((i & 3) << 8) + (i >> 2)] = src[n];
        }
    }
    __syncthreads();

    unsigned long long acc[32];
#pragma unroll
    for (int q = 0; q < 32; q++) acc[q] = 0ull;

    const float4* dbase4 = (const float4*)(D0 + ((long)j0 << 16) + (is << 10));
#pragma unroll 2
    for (int n = 0; n < 16; ++n) {
        int i4 = ig + (n << 4);
        float4 a0 = dbase4[i4];
        float4 a1 = dbase4[16384 + i4];
        float4 a2 = dbase4[32768 + i4];
        float4 a3 = dbase4[49152 + i4];
        float r0[4] = {a0.x, a0.y, a0.z, a0.w};
        float r1[4] = {a1.x, a1.y, a1.z, a1.w};
        float r2[4] = {a2.x, a2.y, a2.z, a2.w};
        float r3[4] = {a3.x, a3.y, a3.z, a3.w};
#pragma unroll
        for (int k = 0; k < 4; ++k) {
            unsigned long long dd0 = pack2(r0[k], r0[k]);
            unsigned long long dd1 = pack2(r1[k], r1[k]);
            unsigned long long dd2 = pack2(r2[k], r2[k]);
            unsigned long long dd3 = pack2(r3[k], r3[k]);
#pragma unroll
            for (int p = 0; p < 8; ++p) {
                unsigned long long s = sb2[(p << 10) + (k << 8) + i4];
                FMA2(acc[p],      dd0, s);
                FMA2(acc[8 + p],  dd1, s);
                FMA2(acc[16 + p], dd2, s);
                FMA2(acc[24 + p], dd3, s);
            }
        }
    }
#pragma unroll
    for (int off = 8; off; off >>= 1)
#pragma unroll
        for (int q = 0; q < 32; q++) {
            unsigned long long v = __shfl_xor_sync(0xffffffffu, acc[q], off);
            ADD2(acc[q], v);
        }
    if (ig == 0) {
#pragma unroll
        for (int q = 0; q < 4; q++) {
            int j = j0 + q;
#pragma unroll
            for (int p = 0; p < 8; p++) {
                float a0, a1; unpack2(acc[q * 8 + p], a0, a1);
                g_part[(is << 13) + ((2 * p)     << 9) + j] = a0;
                g_part[(is << 13) + ((2 * p + 1) << 9) + j] = a1;
            }
        }
    }
}

// ---------------------------------------------------------------------------
// standalone tail epilogue for t=15 (512 threads, 16 blocks)
// ---------------------------------------------------------------------------
__global__ void __launch_bounds__(512) k_tail2(const float* __restrict__ D1,
                                               float* __restrict__ out, int t)
{
    __shared__ float s2[512];
    int b = blockIdx.x;
    int tid = threadIdx.x;
    float I = 0.f;
#pragma unroll 8
    for (int is = 0; is < 64; is++)
        I += g_part[(is << 13) + (b << 9) + tid];
    int idx = (b << 9) + tid;
    float vm;
    if (t) {
        float vp = g_vm2[idx];
        vm = vp * (vp > 0.5f ? 0.f : DECAYF) + I;
    } else vm = I;
    g_vm2[idx] = vm;
    s2[tid] = vm > 0.5f ? 1.f : 0.f;
    __syncthreads();

    int w = tid >> 5, lane = tid & 31;
    if (w < 11) {
        float acc = 0.f;
#pragma unroll
        for (int u = 0; u < 16; u++)
            acc = fmaf(s2[lane + (u << 5)], D1[(w << 9) + lane + (u << 5)], acc);
#pragma unroll
        for (int off = 16; off; off >>= 1)
            acc += __shfl_xor_sync(0xffffffffu, acc, off);
        if (lane == 0) {
            int oidx = b * 11 + w;
            float vm3;
            if (t) {
                float vp = g_vm3[oidx];
                vm3 = vp * (vp > 0.5f ? 0.f : DECAYF) + acc;
            } else vm3 = acc;
            float sp = vm3 > 0.5f ? 1.f : 0.f;
            g_vm3[oidx] = vm3;
            float a = (t ? g_acc[oidx] : 0.f) + sp;
            g_acc[oidx] = a;
            if (t == 15) out[oidx] = a * 0.0625f;
        }
    }
}

// ---------------------------------------------------------------------------
extern "C" void kernel_launch(void* const* d_in, const int* in_sizes, int n_in,
                              void* d_out, int out_size)
{
    (void)in_sizes; (void)n_in; (void)out_size;
    const float* input = (const float*)d_in[0];
    const float* W0    = (const float*)d_in[1];
    const float* W1    = (const float*)d_in[2];
    const float* D0    = (const float*)d_in[3];
    const float* D1    = (const float*)d_in[4];
    float* out = (float*)d_out;

    cudaFuncSetAttribute(k_c1t,  cudaFuncAttributeMaxDynamicSharedMemorySize, 78336);
    cudaFuncSetAttribute(k_d0c0, cudaFuncAttributeMaxDynamicSharedMemorySize, 65536);

    // #0 nop, #1 nop, #2 conv0(0), #3 k_c1t(t=0) (ncu-captured)
    k_nop<<<1, 32>>>();
    k_nop<<<1, 32>>>();
    k_conv0<<<512, 256>>>(input, W0, 0);

    for (int t = 0; t < 16; t++) {
        k_c1t <<<528, 256, 78336>>>(W1, D1, out, t, t - 1);
        k_d0c0<<<1024, 256, 65536>>>(D0, input, W0, t < 15 ? t + 1 : -1);
    }
    k_tail2<<<16, 512>>>(D1, out, 15);
}